// round 5
// baseline (speedup 1.0000x reference)
#include <cuda_runtime.h>

// Conv1dLocal: out[b,o,s] = sum_{i,k} x[b,i,s+k] * w[o,i,s,k]
// B=32, IC=OC=64, S=512, KW=7, STRIDE=1, L=518.
// fp32x2 packed FMAs, b-pairs in lanes. Thread: (s, 4 o) x 8 b-pairs.
// Block: 16 s x 32 o x 16 b x 16 i, 128 threads.
// Grid: 32 s-blocks x 2 o-blocks x (2 b-split * 4 i-split) = 512 blocks.
// i-split partials combined via float atomicAdd (REDG) into zeroed output.

#define B_   32
#define IC_  64
#define OC_  64
#define S_   512
#define KW_  7
#define L_   518

#define S_TILE        16
#define O_PER_THREAD  4
#define OG_PER_BLOCK  8              // 8 groups * 4 = 32 o per block
#define BP_PER_BLOCK  8              // 8 pairs = 16 b per block
#define I_PER_BLOCK   16             // i-split: 4 blocks of 16 i each
#define POS           (S_TILE + KW_ - 1)   // 22
#define THREADS       (S_TILE * OG_PER_BLOCK) // 128
#define XS_ELEMS      (I_PER_BLOCK * BP_PER_BLOCK * POS)  // 2816 = 22 * 128

#define O_STRIDE      ((size_t)IC_ * S_ * KW_)   // weight o-stride in floats

typedef unsigned long long ull;

__device__ __forceinline__ ull pack2(float w) {
    unsigned u = __float_as_uint(w);
    ull r;
    asm("mov.b64 %0, {%1, %1};" : "=l"(r) : "r"(u));
    return r;
}

__device__ __forceinline__ void ffma2(ull &d, ull a, ull b) {
    asm("fma.rn.f32x2 %0, %1, %2, %0;" : "+l"(d) : "l"(a), "l"(b));
}

__global__ __launch_bounds__(THREADS, 4)
void conv1d_local_kernel(const float* __restrict__ x,
                         const float* __restrict__ w,
                         float* __restrict__ out)
{
    // b-pair-interleaved x tile: xs[(i_l*BP + bp)*POS + pos] = {x[2bp], x[2bp+1]}
    __shared__ float2 xs[XS_ELEMS];

    const int tid     = threadIdx.x;
    const int s_local = tid & (S_TILE - 1);
    const int og      = tid >> 4;                 // 0..7
    const int s0      = blockIdx.x * S_TILE;
    const int o_base  = blockIdx.y * (OG_PER_BLOCK * O_PER_THREAD) + og * O_PER_THREAD;
    const int b_blk   = blockIdx.z & 1;
    const int i_blk   = blockIdx.z >> 1;          // 0..3
    const int b0      = b_blk * (2 * BP_PER_BLOCK);
    const int i0      = i_blk * I_PER_BLOCK;
    const int s       = s0 + s_local;

    // cooperative load of x tile: 16 i x 8 b-pairs x 22 pos
    #pragma unroll
    for (int it = 0; it < XS_ELEMS / THREADS; ++it) {
        int t   = it * THREADS + tid;
        int i_l = t / (BP_PER_BLOCK * POS);
        int r   = t - i_l * (BP_PER_BLOCK * POS);
        int bp  = r / POS;
        int pos = r - bp * POS;
        int b   = b0 + 2 * bp;
        const float* xp = x + ((size_t)b * IC_ + (i0 + i_l)) * L_ + s0 + pos;
        xs[t] = make_float2(xp[0], xp[(size_t)IC_ * L_]);
    }
    __syncthreads();

    ull acc[O_PER_THREAD][BP_PER_BLOCK];
    #pragma unroll
    for (int j = 0; j < O_PER_THREAD; j++)
        #pragma unroll
        for (int bp = 0; bp < BP_PER_BLOCK; bp++)
            acc[j][bp] = 0ull;

    const float* wbase = w + (((size_t)o_base * IC_ + i0) * S_ + s) * KW_;

    #pragma unroll 1
    for (int i_l = 0; i_l < I_PER_BLOCK; ++i_l) {
        // batch-load all 28 weights for this i as scalar floats (MLP=28)
        const float* wp0 = wbase + (size_t)i_l * (S_ * KW_);
        const float* wp1 = wp0 + O_STRIDE;
        const float* wp2 = wp1 + O_STRIDE;
        const float* wp3 = wp2 + O_STRIDE;
        float wf[O_PER_THREAD * KW_];
        #pragma unroll
        for (int k = 0; k < KW_; ++k) {
            wf[0 * KW_ + k] = __ldg(&wp0[k]);
            wf[1 * KW_ + k] = __ldg(&wp1[k]);
            wf[2 * KW_ + k] = __ldg(&wp2[k]);
            wf[3 * KW_ + k] = __ldg(&wp3[k]);
        }

        const float2* xb = xs + i_l * (BP_PER_BLOCK * POS) + s_local;
        #pragma unroll
        for (int k = 0; k < KW_; ++k) {
            ull w2[O_PER_THREAD];
            #pragma unroll
            for (int j = 0; j < O_PER_THREAD; ++j)
                w2[j] = pack2(wf[j * KW_ + k]);
            #pragma unroll
            for (int bp = 0; bp < BP_PER_BLOCK; ++bp) {
                ull x2 = *reinterpret_cast<const ull*>(&xb[bp * POS + k]);
                #pragma unroll
                for (int j = 0; j < O_PER_THREAD; ++j)
                    ffma2(acc[j][bp], x2, w2[j]);
            }
        }
    }

    // accumulate partials (4 i-split blocks per output; out pre-zeroed)
    #pragma unroll
    for (int j = 0; j < O_PER_THREAD; ++j) {
        #pragma unroll
        for (int bp = 0; bp < BP_PER_BLOCK; ++bp) {
            float lo = __uint_as_float((unsigned)(acc[j][bp] & 0xffffffffull));
            float hi = __uint_as_float((unsigned)(acc[j][bp] >> 32));
            int b = b0 + 2 * bp;
            atomicAdd(&out[((size_t)b * OC_ + (o_base + j)) * S_ + s], lo);
            atomicAdd(&out[((size_t)(b + 1) * OC_ + (o_base + j)) * S_ + s], hi);
        }
    }
}

extern "C" void kernel_launch(void* const* d_in, const int* in_sizes, int n_in,
                              void* d_out, int out_size)
{
    const float* x = (const float*)d_in[0];
    const float* w = (const float*)d_in[1];
    float* out = (float*)d_out;

    cudaMemsetAsync(out, 0, (size_t)out_size * sizeof(float), 0);

    dim3 grid(S_ / S_TILE,                         // 32
              OC_ / (OG_PER_BLOCK * O_PER_THREAD), // 2
              (B_ / (2 * BP_PER_BLOCK)) * (IC_ / I_PER_BLOCK)); // 2*4 = 8
    conv1d_local_kernel<<<grid, THREADS>>>(x, w, out);
}